// round 5
// baseline (speedup 1.0000x reference)
#include <cuda_runtime.h>
#include <math.h>

#define Bb 4
#define Ss 128
#define Nn 512
#define Hh 64
#define Mm (Bb*Nn)
#define XSTR 68
#define NTH 1024

__device__ float g_Gt[Hh*Hh];  // [h2][h1] = scale * sum_o Wq[o][h1] Wk[o][h2]
__device__ float g_u[Hh];
__device__ float g_w[Hh];
__device__ float g_c0;

__global__ void precompute_k(const float* __restrict__ Wq, const float* __restrict__ bq,
                             const float* __restrict__ Wk, const float* __restrict__ bk) {
    int gid = blockIdx.x * blockDim.x + threadIdx.x;
    const float scale = 0.125f;
    if (gid < Hh * Hh) {
        int h2 = gid >> 6, h1 = gid & 63;
        float s = 0.f;
        #pragma unroll 8
        for (int o = 0; o < Hh; o++) s += Wq[o*Hh + h1] * Wk[o*Hh + h2];
        g_Gt[gid] = s * scale;
    }
    if (gid < Hh) {
        float s = 0.f, t = 0.f;
        #pragma unroll 8
        for (int o = 0; o < Hh; o++) { s += Wq[o*Hh + gid] * bk[o]; t += Wk[o*Hh + gid] * bq[o]; }
        g_u[gid] = s * scale;
        g_w[gid] = t * scale;
    }
    if (gid == 0) {
        float s = 0.f;
        for (int o = 0; o < Hh; o++) s += bq[o] * bk[o];
        g_c0 = s * scale;
    }
}

__device__ __forceinline__ unsigned f2mono(float v) {
    unsigned u = __float_as_uint(v);
    return (u & 0x80000000u) ? ~u : (u | 0x80000000u);
}
__device__ __forceinline__ float mono2f(unsigned k) {
    unsigned u = (k & 0x80000000u) ? (k ^ 0x80000000u) : ~k;
    return __uint_as_float(u);
}
__device__ __forceinline__ float4 lds4(const float* p) { return *(const float4*)p; }

// packed fp32x2 FMA: d = a*b + d elementwise on (lo,hi) -> SASS FFMA2
__device__ __forceinline__ void fma2(unsigned long long& d, unsigned long long a, unsigned long long b) {
    asm("fma.rn.f32x2 %0, %1, %2, %0;" : "+l"(d) : "l"(a), "l"(b));
}
__device__ __forceinline__ float upsum(unsigned long long v) {
    float lo, hi;
    asm("mov.b64 {%0,%1}, %2;" : "=f"(lo), "=f"(hi) : "l"(v));
    return lo + hi;
}

extern __shared__ float smf[];
__global__ void __launch_bounds__(NTH, 1)
fused_align_k(const float* __restrict__ traffic, const float* __restrict__ text,
              const float* __restrict__ Wv, const float* __restrict__ bv,
              const float* __restrict__ gamma, const float* __restrict__ beta,
              const int* __restrict__ topk_p,
              float* __restrict__ out_main, float* __restrict__ out_attn) {
    float* xt_tr = smf;
    float* xt_tx = xt_tr + 128*XSTR;
    float* Pm    = xt_tx + 128*XSTR;
    float* vsm   = Pm    + 128*XSTR;
    float* Gs    = vsm   + 128*XSTR;    // [c][h]
    float* Wvs   = Gs + 4096;           // [c][h]
    float* tail  = Wvs + 4096;
    float* sg  = tail;
    float* sb  = tail + 64;
    float* sbv = tail + 128;
    float* su  = tail + 192;
    float* sw_ = tail + 256;
    float* rb  = tail + 320;
    float* cb  = tail + 448;

    const int tid = threadIdx.x;
    const int lane = tid & 31;
    const int wrp = tid >> 5;
    const int m = blockIdx.x;
    const int b = m >> 9;
    const int n = m & (Nn - 1);

    const float* tr_base = traffic + ((size_t)b * Ss * Nn + n) * Hh;
    const float* tx_base = text    + ((size_t)b * Ss * Nn + n) * Hh;

    // ---- Stage 0 ----
    for (int i = tid; i < 4096; i += NTH) Gs[i]  = g_Gt[i];
    for (int i = tid; i < 4096; i += NTH) Wvs[i] = Wv[i];
    for (int i = tid; i < 128 * 16; i += NTH) {
        int r = i >> 4, f = i & 15;
        *(float4*)(xt_tr + r * XSTR + f * 4) = *(const float4*)(tr_base + (size_t)r * Nn * Hh + f * 4);
        *(float4*)(xt_tx + r * XSTR + f * 4) = *(const float4*)(tx_base + (size_t)r * Nn * Hh + f * 4);
    }
    if (tid < 64) {
        sg[tid] = gamma[tid]; sb[tid] = beta[tid]; sbv[tid] = bv[tid];
        su[tid] = g_u[tid];   sw_[tid] = g_w[tid];
    }
    __syncthreads();

    // ---- Stage 1: bias terms + P GEMM (warps 0-15) + V GEMM (warps 16-31) ----
    if (tid < 128) {
        float s = g_c0;
        const float* xr = xt_tr + tid * XSTR;
        #pragma unroll
        for (int h4 = 0; h4 < 64; h4 += 4) {
            float4 x = lds4(xr + h4), uu = lds4(su + h4);
            s += x.x*uu.x + x.y*uu.y + x.z*uu.z + x.w*uu.w;
        }
        rb[tid] = s;
    } else if (tid < 256) {
        int t2 = tid - 128;
        float s = 0.f;
        const float* xr = xt_tx + t2 * XSTR;
        #pragma unroll
        for (int h4 = 0; h4 < 64; h4 += 4) {
            float4 x = lds4(xr + h4), ww = lds4(sw_ + h4);
            s += x.x*ww.x + x.y*ww.y + x.z*ww.z + x.w*ww.w;
        }
        cb[t2] = s;
    }

    {
        const bool doP = (wrp < 16);
        const int c0 = (doP ? wrp : wrp - 16) * 4;
        const float* X = doP ? xt_tr : xt_tx;
        const float* W = doP ? Gs : Wvs;
        float* D = doP ? Pm : vsm;
        #pragma unroll
        for (int jh = 0; jh < 2; jh++) {                 // column halves -> acc regs stay low
            unsigned long long a2[4][2] = {};
            const float* w0p = W + (c0 + 2*jh) * 64;
            const float* w1p = W + (c0 + 2*jh + 1) * 64;
            #pragma unroll
            for (int h4 = 0; h4 < 64; h4 += 4) {
                ulonglong2 w0 = *(const ulonglong2*)(w0p + h4);   // broadcast LDS.128
                ulonglong2 w1 = *(const ulonglong2*)(w1p + h4);
                #pragma unroll
                for (int i = 0; i < 4; i++) {
                    ulonglong2 x = *(const ulonglong2*)(X + (lane + 32*i) * XSTR + h4);
                    fma2(a2[i][0], x.x, w0.x); fma2(a2[i][0], x.y, w0.y);
                    fma2(a2[i][1], x.x, w1.x); fma2(a2[i][1], x.y, w1.y);
                }
            }
            #pragma unroll
            for (int i = 0; i < 4; i++) {
                float2 o;
                o.x = upsum(a2[i][0]) + (doP ? 0.f : sbv[c0 + 2*jh]);
                o.y = upsum(a2[i][1]) + (doP ? 0.f : sbv[c0 + 2*jh + 1]);
                *(float2*)(D + (lane + 32*i) * XSTR + c0 + 2*jh) = o;
            }
        }
    }
    __syncthreads();

    // ---- Stage 2: scores GEMM into registers (warp rows [4w,4w+4), lane cols lane+32*tj) ----
    const int r0 = wrp * 4;
    float accf[4][4];
    #pragma unroll
    for (int th = 0; th < 2; th++) {                     // tj halves
        unsigned long long a2[4][2] = {};
        const float* xb0p = xt_tx + (lane + 32*(2*th)) * XSTR;
        const float* xb1p = xt_tx + (lane + 32*(2*th + 1)) * XSTR;
        #pragma unroll
        for (int h4 = 0; h4 < 64; h4 += 4) {
            ulonglong2 xb0 = *(const ulonglong2*)(xb0p + h4);
            ulonglong2 xb1 = *(const ulonglong2*)(xb1p + h4);
            #pragma unroll
            for (int ri = 0; ri < 4; ri++) {
                ulonglong2 pv = *(const ulonglong2*)(Pm + (r0 + ri) * XSTR + h4);  // broadcast
                fma2(a2[ri][0], pv.x, xb0.x); fma2(a2[ri][0], pv.y, xb0.y);
                fma2(a2[ri][1], pv.x, xb1.x); fma2(a2[ri][1], pv.y, xb1.y);
            }
        }
        #pragma unroll
        for (int ri = 0; ri < 4; ri++) {
            float rbias = rb[r0 + ri];
            accf[ri][2*th]     = upsum(a2[ri][0]) + rbias + cb[lane + 32*(2*th)];
            accf[ri][2*th + 1] = upsum(a2[ri][1]) + rbias + cb[lane + 32*(2*th + 1)];
        }
    }

    // ---- Stage 3: top-k + softmax + attn + sparse AV + LN ----
    int kk = 16;
    if (topk_p) { kk = topk_p[0]; if (kk < 1) kk = 1; if (kk > 32) kk = 32; }

    float* attn_base = out_attn + (size_t)m * Ss * Ss;
    const unsigned FULL = 0xffffffffu;

    for (int ri = 0; ri < 4; ++ri) {
        const int s = r0 + ri;
        float o0 = accf[ri][0], o1 = accf[ri][1], o2 = accf[ri][2], o3 = accf[ri][3];
        unsigned k0 = f2mono(o0), k1 = f2mono(o1), k2 = f2mono(o2), k3 = f2mono(o3);
        unsigned l0 = k0, l1 = k1, l2 = k2, l3 = k3;
        unsigned maxk = 0, thrk = 0, selk = 0; int seli = 0;

        for (int it = 0; it < kk; ++it) {
            unsigned lb = l0; int slot = 0;
            if (l1 > lb) { lb = l1; slot = 1; }
            if (l2 > lb) { lb = l2; slot = 2; }
            if (l3 > lb) { lb = l3; slot = 3; }
            unsigned mw = __reduce_max_sync(FULL, lb);
            unsigned ball = __ballot_sync(FULL, lb == mw);
            int owner = __ffs(ball) - 1;                       // exact keys; ties ~impossible
            int gidx = __shfl_sync(FULL, slot * 32 + lane, owner);
            if (it == 0) maxk = mw;
            thrk = mw;
            if (lane == owner) {
                if (slot == 0) l0 = 0; else if (slot == 1) l1 = 0;
                else if (slot == 2) l2 = 0; else l3 = 0;
            }
            if (lane == it) { selk = mw; seli = gidx; }
        }

        float maxv = mono2f(maxk);
        float e0 = (k0 >= thrk) ? __expf(o0 - maxv) : 0.f;
        float e1 = (k1 >= thrk) ? __expf(o1 - maxv) : 0.f;
        float e2 = (k2 >= thrk) ? __expf(o2 - maxv) : 0.f;
        float e3 = (k3 >= thrk) ? __expf(o3 - maxv) : 0.f;
        float z = e0 + e1 + e2 + e3;
        #pragma unroll
        for (int off = 16; off > 0; off >>= 1) z += __shfl_xor_sync(FULL, z, off);
        float inv = 1.0f / z;

        float* ab = attn_base + (size_t)s * Ss;
        ab[lane]      = e0 * inv;
        ab[lane + 32] = e1 * inv;
        ab[lane + 64] = e2 * inv;
        ab[lane + 96] = e3 * inv;

        float p = (lane < kk) ? __expf(mono2f(selk) - maxv) * inv : 0.f;
        float a0 = 0.f, a1 = 0.f;
        for (int i2 = 0; i2 < kk; i2++) {
            float pi = __shfl_sync(FULL, p, i2);
            int   ti = __shfl_sync(FULL, seli, i2);
            const float* vr = vsm + ti * XSTR;
            a0 += pi * vr[lane];
            a1 += pi * vr[lane + 32];
        }

        float rr0 = a0 + xt_tr[s * XSTR + lane];
        float rr1 = a1 + xt_tr[s * XSTR + lane + 32];
        float sm1 = rr0 + rr1;
        #pragma unroll
        for (int off = 16; off > 0; off >>= 1) sm1 += __shfl_xor_sync(FULL, sm1, off);
        float mu = sm1 * (1.0f / 64.0f);
        float d0 = rr0 - mu, d1 = rr1 - mu;
        float sq = d0 * d0 + d1 * d1;
        #pragma unroll
        for (int off = 16; off > 0; off >>= 1) sq += __shfl_xor_sync(FULL, sq, off);
        float inv_sd = rsqrtf(sq * (1.0f / 64.0f) + 1e-5f);

        float* ob = out_main + (((size_t)(b * Ss + s)) * Nn + n) * Hh;
        ob[lane]      = d0 * inv_sd * sg[lane]      + sb[lane];
        ob[lane + 32] = d1 * inv_sd * sg[lane + 32] + sb[lane + 32];
    }
}

extern "C" void kernel_launch(void* const* d_in, const int* in_sizes, int n_in,
                              void* d_out, int out_size) {
    const float* traffic = (const float*)d_in[0];
    const float* text    = (const float*)d_in[1];
    const float* Wq      = (const float*)d_in[2];
    const float* bq      = (const float*)d_in[3];
    const float* Wk      = (const float*)d_in[4];
    const float* bk      = (const float*)d_in[5];
    const float* Wv      = (const float*)d_in[6];
    const float* bv      = (const float*)d_in[7];
    const float* gamma   = (const float*)d_in[8];
    const float* beta    = (const float*)d_in[9];
    const int*   topk    = (n_in > 10) ? (const int*)d_in[10] : nullptr;

    float* out  = (float*)d_out;
    float* attn = out + (size_t)Bb * Ss * Nn * Hh;

    size_t smem = (size_t)(4 * 128 * XSTR + 4096 + 4096 + 576) * sizeof(float);
    cudaFuncSetAttribute(fused_align_k, cudaFuncAttributeMaxDynamicSharedMemorySize, (int)smem);

    precompute_k<<<16, 256>>>(Wq, bq, Wk, bk);
    fused_align_k<<<Mm, NTH, smem>>>(traffic, text, Wv, bv, gamma, beta, topk, out, attn);
}

// round 7
// speedup vs baseline: 3.8854x; 3.8854x over previous
#include <cuda_runtime.h>
#include <stdint.h>
#include <math.h>

#define Bb 4
#define Ss 128
#define Nn 512
#define Hh 64
#define Mm 2048
#define XSTR 68
#define SSTR 132
#define NTH 1024

// smem float offsets
#define F_XTR  0          // fp32 [128][68] residual + A of P GEMM
#define F_XTXH 8704       // tf32-hi [128][68]
#define F_XTXL 17408      // tf32-lo [128][68]
#define F_W    26112      // G_h[4352] G_l[4352] Wv_h[4352] Wv_l[4352]; P fp32 overlays first 8704
#define F_VSM  43520      // fp32 [128][68]
#define F_TAIL 52224      // rb128 cb128 sg64 sb64 sbv64
#define F_SC   8704       // scores [128][132] overlay Xtx after S GEMM
#define SMEM_FLOATS (F_TAIL + 448)

// ---------------- precomputed operands ----------------
__device__ float g_Gt[Hh*Hh];      // [c][h] = scale * sum_o Wq[o][h] Wk[o][c]
__device__ float g_u[Hh];
__device__ float g_w[Hh];
__device__ float g_c0;
__device__ __align__(16) float g_Wsplit[4*4352];  // G_h, G_l, Wv_h, Wv_l in [64][68] layout

__global__ void precompute_k(const float* __restrict__ Wq, const float* __restrict__ bq,
                             const float* __restrict__ Wk, const float* __restrict__ bk) {
    int gid = blockIdx.x * blockDim.x + threadIdx.x;
    const float scale = 0.125f;
    if (gid < Hh * Hh) {
        int c = gid >> 6, h = gid & 63;
        float s = 0.f;
        #pragma unroll 8
        for (int o = 0; o < Hh; o++) s += Wq[o*Hh + h] * Wk[o*Hh + c];
        g_Gt[gid] = s * scale;
    }
    if (gid < Hh) {
        float s = 0.f, t = 0.f;
        #pragma unroll 8
        for (int o = 0; o < Hh; o++) { s += Wq[o*Hh + gid] * bk[o]; t += Wk[o*Hh + gid] * bq[o]; }
        g_u[gid] = s * scale;
        g_w[gid] = t * scale;
    }
    if (gid == 0) {
        float s = 0.f;
        for (int o = 0; o < Hh; o++) s += bq[o] * bk[o];
        g_c0 = s * scale;
    }
}

__device__ __forceinline__ void tf32x2(float x, uint32_t& h, uint32_t& l) {
    asm("cvt.rna.tf32.f32 %0, %1;" : "=r"(h) : "f"(x));
    float r = x - __uint_as_float(h);
    asm("cvt.rna.tf32.f32 %0, %1;" : "=r"(l) : "f"(r));
}

// split G ([c][h]) and Wv ([c][h], row-major as-is) into tf32 hi/lo, [64][68] padded
__global__ void precompute_pack(const float* __restrict__ Wv) {
    int gid = blockIdx.x * blockDim.x + threadIdx.x;
    if (gid >= 2 * 4352) return;
    int mat = gid / 4352;          // 0: G, 1: Wv
    int rem = gid % 4352;
    int r = rem / XSTR, c = rem % XSTR;
    float v = 0.f;
    if (c < 64) v = mat ? Wv[r*64 + c] : g_Gt[r*64 + c];
    uint32_t h, l;
    tf32x2(v, h, l);
    g_Wsplit[mat*8704 + rem]        = __uint_as_float(h);
    g_Wsplit[mat*8704 + 4352 + rem] = __uint_as_float(l);
}

// ---------------- mma helpers ----------------
__device__ __forceinline__ void mma8(float c[4], const uint32_t a[4], uint32_t b0, uint32_t b1) {
    asm volatile(
        "mma.sync.aligned.m16n8k8.row.col.f32.tf32.tf32.f32 "
        "{%0,%1,%2,%3}, {%4,%5,%6,%7}, {%8,%9}, {%0,%1,%2,%3};"
        : "+f"(c[0]), "+f"(c[1]), "+f"(c[2]), "+f"(c[3])
        : "r"(a[0]), "r"(a[1]), "r"(a[2]), "r"(a[3]), "r"(b0), "r"(b1));
}

// A fp32 (split on the fly), B pre-split hi/lo; warp tile m16 x n32, K=64
__device__ __forceinline__ void gemm_fly(const float* __restrict__ A,
                                         const float* __restrict__ Bh, const float* __restrict__ Bl,
                                         int mb, int n0, int lane, float acc[4][4]) {
    const int g = lane >> 2, q = lane & 3;
    const float* ar0 = A + (mb + g) * XSTR + q;
    const float* ar1 = A + (mb + g + 8) * XSTR + q;
    #pragma unroll
    for (int k0 = 0; k0 < 64; k0 += 8) {
        uint32_t ah[4], al[4];
        tf32x2(ar0[k0],   ah[0], al[0]);
        tf32x2(ar1[k0],   ah[1], al[1]);
        tf32x2(ar0[k0+4], ah[2], al[2]);
        tf32x2(ar1[k0+4], ah[3], al[3]);
        #pragma unroll
        for (int nt = 0; nt < 4; nt++) {
            int bi = (n0 + 8*nt + g) * XSTR + k0 + q;
            uint32_t b0h = __float_as_uint(Bh[bi]), b1h = __float_as_uint(Bh[bi+4]);
            uint32_t b0l = __float_as_uint(Bl[bi]), b1l = __float_as_uint(Bl[bi+4]);
            mma8(acc[nt], ah, b0h, b1h);
            mma8(acc[nt], ah, b0l, b1l);
            mma8(acc[nt], al, b0h, b1h);
        }
    }
}

// A pre-split hi/lo, B pre-split hi/lo
__device__ __forceinline__ void gemm_ps(const float* __restrict__ Ah, const float* __restrict__ Al,
                                        const float* __restrict__ Bh, const float* __restrict__ Bl,
                                        int mb, int n0, int lane, float acc[4][4]) {
    const int g = lane >> 2, q = lane & 3;
    const int r0 = (mb + g) * XSTR + q, r1 = (mb + g + 8) * XSTR + q;
    #pragma unroll
    for (int k0 = 0; k0 < 64; k0 += 8) {
        uint32_t ah[4], al[4];
        ah[0] = __float_as_uint(Ah[r0 + k0]);   al[0] = __float_as_uint(Al[r0 + k0]);
        ah[1] = __float_as_uint(Ah[r1 + k0]);   al[1] = __float_as_uint(Al[r1 + k0]);
        ah[2] = __float_as_uint(Ah[r0 + k0+4]); al[2] = __float_as_uint(Al[r0 + k0+4]);
        ah[3] = __float_as_uint(Ah[r1 + k0+4]); al[3] = __float_as_uint(Al[r1 + k0+4]);
        #pragma unroll
        for (int nt = 0; nt < 4; nt++) {
            int bi = (n0 + 8*nt + g) * XSTR + k0 + q;
            uint32_t b0h = __float_as_uint(Bh[bi]), b1h = __float_as_uint(Bh[bi+4]);
            uint32_t b0l = __float_as_uint(Bl[bi]), b1l = __float_as_uint(Bl[bi+4]);
            mma8(acc[nt], ah, b0h, b1h);
            mma8(acc[nt], ah, b0l, b1l);
            mma8(acc[nt], al, b0h, b1h);
        }
    }
}

__device__ __forceinline__ unsigned f2mono(float v) {
    unsigned u = __float_as_uint(v);
    return (u & 0x80000000u) ? ~u : (u | 0x80000000u);
}
__device__ __forceinline__ float mono2f(unsigned k) {
    unsigned u = (k & 0x80000000u) ? (k ^ 0x80000000u) : ~k;
    return __uint_as_float(u);
}

extern __shared__ float smf[];
__global__ void __launch_bounds__(NTH, 1)
fused_align_k(const float* __restrict__ traffic, const float* __restrict__ text,
              const float* __restrict__ Wv, const float* __restrict__ bv,
              const float* __restrict__ gamma, const float* __restrict__ beta,
              const int* __restrict__ topk_p,
              float* __restrict__ out_main, float* __restrict__ out_attn) {
    float* xt_tr = smf + F_XTR;
    float* xtxh  = smf + F_XTXH;
    float* xtxl  = smf + F_XTXL;
    float* Wr    = smf + F_W;        // G_h | G_l | Wv_h | Wv_l ; P overlays [0..8704)
    float* vsm   = smf + F_VSM;
    float* sc    = smf + F_SC;
    float* rb  = smf + F_TAIL;
    float* cb  = rb + 128;
    float* sg  = cb + 128;
    float* sb  = sg + 64;
    float* sbv = sb + 64;

    const int tid = threadIdx.x;
    const int lane = tid & 31;
    const int wrp = tid >> 5;
    const int m = blockIdx.x;
    const int b = m >> 9;
    const int n = m & (Nn - 1);

    const float* tr_base = traffic + ((size_t)b * Ss * Nn + n) * Hh;
    const float* tx_base = text    + ((size_t)b * Ss * Nn + n) * Hh;

    // ---- Stage 0: weights copy, tiles, biases ----
    for (int i = tid; i < 4352; i += NTH)
        ((uint4*)Wr)[i] = ((const uint4*)g_Wsplit)[i];
    #pragma unroll
    for (int it = 0; it < 2; it++) {
        int i = tid + it * NTH;
        int r = i >> 4, f = i & 15;
        float4 a  = *(const float4*)(tr_base + (size_t)r * Nn * Hh + f * 4);
        float4 bx = *(const float4*)(tx_base + (size_t)r * Nn * Hh + f * 4);
        *(float4*)(xt_tr + r * XSTR + f * 4) = a;
        // split Xtx -> tf32 hi/lo
        uint32_t h0,l0,h1,l1,h2,l2,h3,l3;
        tf32x2(bx.x,h0,l0); tf32x2(bx.y,h1,l1); tf32x2(bx.z,h2,l2); tf32x2(bx.w,h3,l3);
        float4 hv, lv;
        hv.x=__uint_as_float(h0); hv.y=__uint_as_float(h1); hv.z=__uint_as_float(h2); hv.w=__uint_as_float(h3);
        lv.x=__uint_as_float(l0); lv.y=__uint_as_float(l1); lv.z=__uint_as_float(l2); lv.w=__uint_as_float(l3);
        *(float4*)(xtxh + r * XSTR + f * 4) = hv;
        *(float4*)(xtxl + r * XSTR + f * 4) = lv;
        // fused bias partials (16 lanes per row)
        float4 uu = *(const float4*)(g_u + f * 4);
        float4 ww = *(const float4*)(g_w + f * 4);
        float pr = a.x*uu.x + a.y*uu.y + a.z*uu.z + a.w*uu.w;
        float pc = bx.x*ww.x + bx.y*ww.y + bx.z*ww.z + bx.w*ww.w;
        #pragma unroll
        for (int o = 8; o > 0; o >>= 1) {
            pr += __shfl_xor_sync(0xffffffffu, pr, o);
            pc += __shfl_xor_sync(0xffffffffu, pc, o);
        }
        if (f == 0) { rb[r] = pr + g_c0; cb[r] = pc; }
    }
    if (tid < 64) { sg[tid] = gamma[tid]; sb[tid] = beta[tid]; sbv[tid] = bv[tid]; }
    __syncthreads();

    const int g = lane >> 2, q = lane & 3;

    // ---- Phase 1: P GEMM (warps 0-15) / V GEMM (warps 16-31) ----
    float accPV[4][4];
    #pragma unroll
    for (int i = 0; i < 4; i++)
        #pragma unroll
        for (int j = 0; j < 4; j++) accPV[i][j] = 0.f;
    {
        int w2 = (wrp < 16) ? wrp : (wrp - 16);
        int mb = (w2 >> 1) * 16, n0 = (w2 & 1) * 32;
        if (wrp < 16) {
            gemm_fly(xt_tr, Wr, Wr + 4352, mb, n0, lane, accPV);     // P = Xtr @ G^T(B)
        } else {
            gemm_ps(xtxh, xtxl, Wr + 8704, Wr + 13056, mb, n0, lane, accPV);  // V
            // store V (+bv) immediately; vsm untouched by others
            #pragma unroll
            for (int nt = 0; nt < 4; nt++) {
                int col = n0 + 8*nt + 2*q;
                float2 o0 = { accPV[nt][0] + sbv[col], accPV[nt][1] + sbv[col+1] };
                float2 o1 = { accPV[nt][2] + sbv[col], accPV[nt][3] + sbv[col+1] };
                *(float2*)(vsm + (mb + g) * XSTR + col)     = o0;
                *(float2*)(vsm + (mb + g + 8) * XSTR + col) = o1;
            }
        }
    }
    __syncthreads();   // all G/Wv reads done
    if (wrp < 16) {    // store P fp32 over G region
        int mb = (wrp >> 1) * 16, n0 = (wrp & 1) * 32;
        #pragma unroll
        for (int nt = 0; nt < 4; nt++) {
            int col = n0 + 8*nt + 2*q;
            float2 o0 = { accPV[nt][0], accPV[nt][1] };
            float2 o1 = { accPV[nt][2], accPV[nt][3] };
            *(float2*)(Wr + (mb + g) * XSTR + col)     = o0;
            *(float2*)(Wr + (mb + g + 8) * XSTR + col) = o1;
        }
    }
    __syncthreads();   // P visible

    // ---- Phase 2: S GEMM (all 32 warps; m16 x n32 tiles) ----
    float accS[4][4];
    #pragma unroll
    for (int i = 0; i < 4; i++)
        #pragma unroll
        for (int j = 0; j < 4; j++) accS[i][j] = 0.f;
    const int smb = (wrp >> 2) * 16, sn0 = (wrp & 3) * 32;
    gemm_fly(Wr, xtxh, xtxl, smb, sn0, lane, accS);
    __syncthreads();   // all Xtx/P reads done -> safe to overlay scores
    #pragma unroll
    for (int nt = 0; nt < 4; nt++) {
        int col = sn0 + 8*nt + 2*q;
        float2 o0 = { accS[nt][0], accS[nt][1] };
        float2 o1 = { accS[nt][2], accS[nt][3] };
        *(float2*)(sc + (smb + g) * SSTR + col)     = o0;
        *(float2*)(sc + (smb + g + 8) * SSTR + col) = o1;
    }
    __syncthreads();

    // ---- Stage 3: per-row top-k + softmax + attn + sparse AV + LN ----
    int kk = 16;
    if (topk_p) { kk = topk_p[0]; if (kk < 1) kk = 1; if (kk > 32) kk = 32; }

    const int r0 = wrp * 4;
    float* attn_base = out_attn + (size_t)m * Ss * Ss;
    const unsigned FULL = 0xffffffffu;

    for (int ri = 0; ri < 4; ++ri) {
        const int s = r0 + ri;
        const float rbias = rb[s];
        float o0 = sc[s * SSTR + lane]      + rbias + cb[lane];
        float o1 = sc[s * SSTR + lane + 32] + rbias + cb[lane + 32];
        float o2 = sc[s * SSTR + lane + 64] + rbias + cb[lane + 64];
        float o3 = sc[s * SSTR + lane + 96] + rbias + cb[lane + 96];
        unsigned k0 = f2mono(o0), k1 = f2mono(o1), k2 = f2mono(o2), k3 = f2mono(o3);
        unsigned l0 = k0, l1 = k1, l2 = k2, l3 = k3;
        unsigned maxk = 0, thrk = 0, selk = 0; int seli = 0;

        for (int it = 0; it < kk; ++it) {
            unsigned lb = l0; int slot = 0;
            if (l1 > lb) { lb = l1; slot = 1; }
            if (l2 > lb) { lb = l2; slot = 2; }
            if (l3 > lb) { lb = l3; slot = 3; }
            unsigned mw = __reduce_max_sync(FULL, lb);
            unsigned cand = (lb == mw) ? (unsigned)(slot * 32 + lane) : 0xffffffffu;
            unsigned tsel = __reduce_min_sync(FULL, cand);
            if (it == 0) maxk = mw;
            thrk = mw;
            if (lane == (int)(tsel & 31)) {
                int js = tsel >> 5;
                if (js == 0) l0 = 0; else if (js == 1) l1 = 0;
                else if (js == 2) l2 = 0; else l3 = 0;
            }
            if (lane == it) { selk = mw; seli = (int)tsel; }
        }

        float maxv = mono2f(maxk);
        float e0 = (k0 >= thrk) ? __expf(o0 - maxv) : 0.f;
        float e1 = (k1 >= thrk) ? __expf(o1 - maxv) : 0.f;
        float e2 = (k2 >= thrk) ? __expf(o2 - maxv) : 0.f;
        float e3 = (k3 >= thrk) ? __expf(o3 - maxv) : 0.f;
        float z = e0 + e1 + e2 + e3;
        #pragma unroll
        for (int off = 16; off > 0; off >>= 1) z += __shfl_xor_sync(FULL, z, off);
        float inv = 1.0f / z;

        float* ab = attn_base + (size_t)s * Ss;
        ab[lane]      = e0 * inv;
        ab[lane + 32] = e1 * inv;
        ab[lane + 64] = e2 * inv;
        ab[lane + 96] = e3 * inv;

        float p = (lane < kk) ? __expf(mono2f(selk) - maxv) * inv : 0.f;
        float a0 = 0.f, a1 = 0.f;
        for (int i2 = 0; i2 < kk; i2++) {
            float pi = __shfl_sync(FULL, p, i2);
            int   ti = __shfl_sync(FULL, seli, i2);
            const float* vr = vsm + ti * XSTR;
            a0 += pi * vr[lane];
            a1 += pi * vr[lane + 32];
        }

        float rr0 = a0 + xt_tr[s * XSTR + lane];
        float rr1 = a1 + xt_tr[s * XSTR + lane + 32];
        float sm1 = rr0 + rr1;
        #pragma unroll
        for (int off = 16; off > 0; off >>= 1) sm1 += __shfl_xor_sync(FULL, sm1, off);
        float mu = sm1 * (1.0f / 64.0f);
        float d0 = rr0 - mu, d1 = rr1 - mu;
        float sq = d0 * d0 + d1 * d1;
        #pragma unroll
        for (int off = 16; off > 0; off >>= 1) sq += __shfl_xor_sync(FULL, sq, off);
        float inv_sd = rsqrtf(sq * (1.0f / 64.0f) + 1e-5f);

        float* ob = out_main + (((size_t)(b * Ss + s)) * Nn + n) * Hh;
        ob[lane]      = d0 * inv_sd * sg[lane]      + sb[lane];
        ob[lane + 32] = d1 * inv_sd * sg[lane + 32] + sb[lane + 32];
    }
}

extern "C" void kernel_launch(void* const* d_in, const int* in_sizes, int n_in,
                              void* d_out, int out_size) {
    const float* traffic = (const float*)d_in[0];
    const float* text    = (const float*)d_in[1];
    const float* Wq      = (const float*)d_in[2];
    const float* bq      = (const float*)d_in[3];
    const float* Wk      = (const float*)d_in[4];
    const float* bk      = (const float*)d_in[5];
    const float* Wv      = (const float*)d_in[6];
    const float* bv      = (const float*)d_in[7];
    const float* gamma   = (const float*)d_in[8];
    const float* beta    = (const float*)d_in[9];
    const int*   topk    = (n_in > 10) ? (const int*)d_in[10] : nullptr;

    float* out  = (float*)d_out;
    float* attn = out + (size_t)Bb * Ss * Nn * Hh;

    size_t smem = (size_t)SMEM_FLOATS * sizeof(float);   // ~206 KB
    cudaFuncSetAttribute(fused_align_k, cudaFuncAttributeMaxDynamicSharedMemorySize, (int)smem);

    precompute_k<<<16, 256>>>(Wq, bq, Wk, bk);
    precompute_pack<<<34, 256>>>(Wv);
    fused_align_k<<<Mm, NTH, smem>>>(traffic, text, Wv, bv, gamma, beta, topk, out, attn);
}